// round 2
// baseline (speedup 1.0000x reference)
#include <cuda_runtime.h>
#include <math.h>

#define NB 64
#define MB 32
#define NM (NB*MB)      // 2048 node rows
#define FEATD 256
#define POSD 6
#define DD 262
#define DD2 524
#define MSGD 128
#define NCLSD 7
#define G3 (3*DD)       // 786

// ---------------- scratch (static device memory; no allocation) ----------------
__device__ float g_nf [NM*DD];
__device__ float g_h  [NM*DD];
__device__ float g_AB [NM*DD2];       // [A | B] per row
__device__ float g_Wab[DD2*DD];       // packed [W1a; W1b], 524 x 262
__device__ float g_att[NB*MB*MB];
__device__ float g_msg[NM*MSGD];
__device__ float g_mv [NM*MSGD];
__device__ float g_gx [NM*G3];
__device__ float g_gh [NM*G3];
__device__ float g_t  [NM*MSGD];

__device__ __forceinline__ float sigmoidf(float x) {
    return 1.0f / (1.0f + expf(-x));
}

// ---------------- build nf = [feat, pos], h = nf ----------------
__global__ void build_nf_kernel(const float* __restrict__ feat,
                                const float* __restrict__ pos) {
    int idx = blockIdx.x * blockDim.x + threadIdx.x;
    if (idx >= NM * DD) return;
    int row = idx / DD, c = idx % DD;
    float v = (c < FEATD) ? feat[row * FEATD + c] : pos[row * POSD + (c - FEATD)];
    g_nf[idx] = v;
    g_h[idx]  = v;
}

// ---------------- pack Wab = [W1 cols 0..261 ; W1 cols 262..523] ----------------
__global__ void pack_wab_kernel(const float* __restrict__ w1) {
    int idx = blockIdx.x * blockDim.x + threadIdx.x;
    if (idx >= DD2 * DD) return;
    int n = idx / DD, k = idx % DD;
    g_Wab[idx] = (n < DD) ? w1[n * DD2 + k] : w1[(n - DD) * DD2 + DD + k];
}

// ---------------- GEMM: C = A * W^T (+bias)(+relu), 64x64 tile, 8x8 microtile ----------------
// A: M x K (lda), W: N x K (ldw), C: M x N (ldc). 64 threads/block.
#define KS 16
template<int RELU>
__global__ void gemm64_kernel(const float* __restrict__ A, int lda,
                              const float* __restrict__ W, int ldw,
                              const float* __restrict__ bias,
                              float* __restrict__ C, int ldc,
                              int M, int N, int K) {
    __shared__ float As[KS][64];
    __shared__ float Ws[KS][64];
    int tid = threadIdx.x;            // 0..63
    int tx = tid & 7, ty = tid >> 3;  // 8 x 8 thread grid
    int m0 = blockIdx.y * 64, n0 = blockIdx.x * 64;

    float acc[8][8] = {};

    for (int k0 = 0; k0 < K; k0 += KS) {
        // stage A tile: 64 rows x 16 k, each thread handles 2 half-rows of 8 k
        #pragma unroll
        for (int i = tid; i < 128; i += 64) {
            int mm = i >> 1, kb = (i & 1) * 8;
            int m = m0 + mm;
            const float* ap = A + (size_t)m * lda + k0 + kb;
            #pragma unroll
            for (int j = 0; j < 8; j++) {
                int k = k0 + kb + j;
                As[kb + j][mm] = (m < M && k < K) ? ap[j] : 0.0f;
            }
        }
        #pragma unroll
        for (int i = tid; i < 128; i += 64) {
            int nn = i >> 1, kb = (i & 1) * 8;
            int n = n0 + nn;
            const float* wp = W + (size_t)n * ldw + k0 + kb;
            #pragma unroll
            for (int j = 0; j < 8; j++) {
                int k = k0 + kb + j;
                Ws[kb + j][nn] = (n < N && k < K) ? wp[j] : 0.0f;
            }
        }
        __syncthreads();
        #pragma unroll
        for (int kk = 0; kk < KS; kk++) {
            float a[8], w[8];
            *(float4*)&a[0] = *(const float4*)&As[kk][ty * 8];
            *(float4*)&a[4] = *(const float4*)&As[kk][ty * 8 + 4];
            *(float4*)&w[0] = *(const float4*)&Ws[kk][tx * 8];
            *(float4*)&w[4] = *(const float4*)&Ws[kk][tx * 8 + 4];
            #pragma unroll
            for (int i = 0; i < 8; i++)
                #pragma unroll
                for (int j = 0; j < 8; j++)
                    acc[i][j] = fmaf(a[i], w[j], acc[i][j]);
        }
        __syncthreads();
    }

    #pragma unroll
    for (int i = 0; i < 8; i++) {
        int m = m0 + ty * 8 + i;
        if (m >= M) continue;
        #pragma unroll
        for (int j = 0; j < 8; j++) {
            int n = n0 + tx * 8 + j;
            if (n >= N) continue;
            float v = acc[i][j] + (bias ? bias[n] : 0.0f);
            if (RELU) v = fmaxf(v, 0.0f);
            C[(size_t)m * ldc + n] = v;
        }
    }
}

// ---------------- attention: one block per batch b, A/B tiles in shared ----------------
// att[b,n,w] = sigmoid(b2 + sum_d w2[d] * relu(A[b,n,d] + B[b,w,d] + b1[d])) for valid,
// else sigmoid(b2 + sum_d w2[d] * relu(b1[d]))
#define ATT_LD 264
__global__ void att_kernel(const float* __restrict__ b1,
                           const float* __restrict__ w2,
                           const float* __restrict__ b2v,
                           const int* __restrict__ num_rec,
                           float* __restrict__ att_out) {
    extern __shared__ float s[];
    float* sA = s;                    // 32 x 264
    float* sB = s + 32 * ATT_LD;      // 32 x 264
    float* sW = s + 64 * ATT_LD;      // 262
    __shared__ float s_cb;

    int b = blockIdx.x;
    int tid = threadIdx.x;            // 0..255
    int lane = tid & 31, warp = tid >> 5;
    float b2 = b2v[0];

    for (int i = tid; i < MB * DD; i += 256) {
        int n = i / DD, d = i % DD;
        const float* row = g_AB + (size_t)(b * MB + n) * DD2;
        sA[n * ATT_LD + d] = row[d] + b1[d];
        sB[n * ATT_LD + d] = row[DD + d];
    }
    for (int d = tid; d < DD; d += 256) sW[d] = w2[d];
    __syncthreads();

    if (warp == 0) {
        float cs = 0.0f;
        for (int d = lane; d < DD; d += 32) cs += fmaxf(b1[d], 0.0f) * sW[d];
        #pragma unroll
        for (int o = 16; o > 0; o >>= 1) cs += __shfl_xor_sync(0xffffffffu, cs, o);
        if (lane == 0) s_cb = sigmoidf(cs + b2);
    }
    __syncthreads();

    int nr = num_rec[b];
    float cb = s_cb;
    for (int p = warp; p < MB * MB; p += 8) {
        int n = p >> 5, w = p & 31;
        float a;
        if (n < nr && w < nr) {
            const float* ra = sA + n * ATT_LD;
            const float* rb = sB + w * ATT_LD;
            float sacc = 0.0f;
            for (int d = lane; d < DD; d += 32)
                sacc += fmaxf(ra[d] + rb[d], 0.0f) * sW[d];
            #pragma unroll
            for (int o = 16; o > 0; o >>= 1) sacc += __shfl_xor_sync(0xffffffffu, sacc, o);
            a = sigmoidf(sacc + b2);
        } else {
            a = cb;
        }
        if (lane == 0) {
            g_att[b * MB * MB + p] = a;
            att_out[b * MB * MB + p] = a;
        }
    }
}

// ---------------- mv[b,n,k] = sum_{w < nr_b} att[b,n,w] * msg[b,w,k] ----------------
__global__ void mv_kernel(const int* __restrict__ num_rec) {
    int bn = blockIdx.x;              // 0..2047
    int b = bn >> 5;
    int k = threadIdx.x;              // 0..127
    int nr = num_rec[b];
    const float* arow = g_att + (size_t)bn * MB;
    const float* mb = g_msg + (size_t)b * MB * MSGD;
    float s = 0.0f;
    for (int w = 0; w < nr; w++) s = fmaf(arow[w], mb[w * MSGD + k], s);
    g_mv[(size_t)bn * MSGD + k] = s;
}

// ---------------- GRU combine (in-place h update, vmask) ----------------
__global__ void gru_kernel(const int* __restrict__ num_rec) {
    int idx = blockIdx.x * blockDim.x + threadIdx.x;
    if (idx >= NM * DD) return;
    int row = idx / DD, d = idx % DD;
    int b = row >> 5, m = row & 31;
    size_t base = (size_t)row * G3;
    float xr = g_gx[base + d];
    float xz = g_gx[base + DD + d];
    float xn = g_gx[base + 2 * DD + d];
    float hr = g_gh[base + d];
    float hz = g_gh[base + DD + d];
    float hn = g_gh[base + 2 * DD + d];
    float r = sigmoidf(xr + hr);
    float z = sigmoidf(xz + hz);
    float c = tanhf(xn + r * hn);
    float hv = g_h[idx];
    float out = (1.0f - z) * c + z * hv;
    g_h[idx] = (m < num_rec[b]) ? out : 0.0f;
}

// ---------------- readout layer 2: pred = t @ ro_w2^T + ro_b2, vmask ----------------
__global__ void pred_kernel(const float* __restrict__ w2,
                            const float* __restrict__ b2,
                            const int* __restrict__ num_rec,
                            float* __restrict__ out) {
    int idx = blockIdx.x * blockDim.x + threadIdx.x;
    if (idx >= NM * NCLSD) return;
    int row = idx / NCLSD, c = idx % NCLSD;
    int b = row >> 5, m = row & 31;
    const float* tr = g_t + (size_t)row * MSGD;
    const float* wr = w2 + (size_t)c * MSGD;
    float s = b2[c];
    #pragma unroll 4
    for (int k = 0; k < MSGD; k++) s = fmaf(tr[k], wr[k], s);
    out[idx] = (m < num_rec[b]) ? s : 0.0f;
}

// ---------------- host launcher ----------------
static void launch_gemm(const float* A, int lda, const float* W, int ldw,
                        const float* bias, float* C, int ldc,
                        int M, int N, int K, int relu_flag) {
    dim3 grid((N + 63) / 64, (M + 63) / 64);
    if (relu_flag)
        gemm64_kernel<1><<<grid, 64>>>(A, lda, W, ldw, bias, C, ldc, M, N, K);
    else
        gemm64_kernel<0><<<grid, 64>>>(A, lda, W, ldw, bias, C, ldc, M, N, K);
}

extern "C" void kernel_launch(void* const* d_in, const int* in_sizes, int n_in,
                              void* d_out, int out_size) {
    const float* feat    = (const float*)d_in[0];
    const float* pos     = (const float*)d_in[1];
    const int*   num_rec = (const int*)  d_in[2];
    const float* link_w1 = (const float*)d_in[3];
    const float* link_b1 = (const float*)d_in[4];
    const float* link_w2 = (const float*)d_in[5];
    const float* link_b2 = (const float*)d_in[6];
    const float* msg_w   = (const float*)d_in[7];
    const float* msg_b   = (const float*)d_in[8];
    const float* gru_w_ih= (const float*)d_in[9];
    const float* gru_w_hh= (const float*)d_in[10];
    const float* gru_b_ih= (const float*)d_in[11];
    const float* gru_b_hh= (const float*)d_in[12];
    const float* ro_w1   = (const float*)d_in[13];
    const float* ro_b1   = (const float*)d_in[14];
    const float* ro_w2   = (const float*)d_in[15];
    const float* ro_b2   = (const float*)d_in[16];
    float* out = (float*)d_out;           // [pred (64*32*7) | attmat (64*32*32)]

    float *p_nf, *p_h, *p_AB, *p_Wab, *p_msg, *p_mv, *p_gx, *p_gh, *p_t;
    cudaGetSymbolAddress((void**)&p_nf,  g_nf);
    cudaGetSymbolAddress((void**)&p_h,   g_h);
    cudaGetSymbolAddress((void**)&p_AB,  g_AB);
    cudaGetSymbolAddress((void**)&p_Wab, g_Wab);
    cudaGetSymbolAddress((void**)&p_msg, g_msg);
    cudaGetSymbolAddress((void**)&p_mv,  g_mv);
    cudaGetSymbolAddress((void**)&p_gx,  g_gx);
    cudaGetSymbolAddress((void**)&p_gh,  g_gh);
    cudaGetSymbolAddress((void**)&p_t,   g_t);

    // allow >48KB dynamic shared for att_kernel (idempotent, host-side)
    static const size_t ATT_SMEM = (size_t)(64 * ATT_LD + 272) * sizeof(float);
    cudaFuncSetAttribute(att_kernel, cudaFuncAttributeMaxDynamicSharedMemorySize,
                         (int)ATT_SMEM);

    // 1) nf = [feat, pos]; h = nf; pack Wab
    build_nf_kernel<<<(NM * DD + 255) / 256, 256>>>(feat, pos);
    pack_wab_kernel<<<(DD2 * DD + 255) / 256, 256>>>(link_w1);

    // 2) low-rank edge MLP in one GEMM: AB = nf @ Wab^T  (2048 x 524)
    launch_gemm(p_nf, DD, p_Wab, DD, nullptr, p_AB, DD2, NM, DD2, DD, 0);

    // 3) attention per pair
    att_kernel<<<NB, 256, ATT_SMEM>>>(link_b1, link_w2, link_b2,
                                      num_rec, out + NM * NCLSD);

    // 4) two message-passing GRU rounds
    for (int round = 0; round < 2; round++) {
        launch_gemm(p_h,  DD,   msg_w,    DD,   msg_b,    p_msg, MSGD, NM, MSGD, DD,   0);
        mv_kernel<<<NM, MSGD>>>(num_rec);
        launch_gemm(p_mv, MSGD, gru_w_ih, MSGD, gru_b_ih, p_gx,  G3,   NM, G3,   MSGD, 0);
        launch_gemm(p_h,  DD,   gru_w_hh, DD,   gru_b_hh, p_gh,  G3,   NM, G3,   DD,   0);
        gru_kernel<<<(NM * DD + 255) / 256, 256>>>(num_rec);
    }

    // 5) readout
    launch_gemm(p_h, DD, ro_w1, DD, ro_b1, p_t, MSGD, NM, MSGD, DD, 1);
    pred_kernel<<<(NM * NCLSD + 127) / 128, 128>>>(ro_w2, ro_b2, num_rec, out);

    (void)in_sizes; (void)n_in; (void)out_size;
}

// round 3
// speedup vs baseline: 1.4741x; 1.4741x over previous
#include <cuda_runtime.h>
#include <math.h>

#define NB 64
#define MB 32
#define NM (NB*MB)      // 2048 node rows
#define FEATD 256
#define POSD 6
#define DD 262
#define DD2 524
#define MSGD 128
#define NCLSD 7
#define G3 (3*DD)       // 786
#define NMG (MSGD + G3) // 914 fused msg|gh width

// ---------------- scratch (static device memory; zero-initialized) ----------------
__device__ float g_nf  [NM*DD];
__device__ float g_h   [NM*DD];
__device__ float g_AB  [NM*DD2];        // [A+b1 | B] per row, stride 524
__device__ float g_Wab [DD2*DD];        // packed [W1a; W1b]
__device__ float g_bab [DD2];           // [b1 | 0]
__device__ float g_Wmg [NMG*DD];        // packed [msg_w; gru_w_hh]
__device__ float g_bmg [NMG];           // [msg_b | gru_b_hh]
__device__ float g_mg  [NM*NMG];        // [msg | gh], stride 914
__device__ float g_att [NB*MB*MB];
__device__ float g_mv  [NM*MSGD];
__device__ float g_gx  [NM*G3];
__device__ float g_zero[DD];            // stays zero forever

__device__ __forceinline__ float sigmoidf(float x) {
    return 1.0f / (1.0f + expf(-x));
}

// ---------------- build nf = [feat, pos], h = nf ----------------
__global__ void build_nf_kernel(const float* __restrict__ feat,
                                const float* __restrict__ pos) {
    int idx = blockIdx.x * blockDim.x + threadIdx.x;
    if (idx >= NM * DD) return;
    int row = idx / DD, c = idx % DD;
    float v = (c < FEATD) ? feat[row * FEATD + c] : pos[row * POSD + (c - FEATD)];
    g_nf[idx] = v;
    g_h[idx]  = v;
}

// ---------------- pack fused weight/bias buffers ----------------
__global__ void pack_kernel(const float* __restrict__ link_w1,
                            const float* __restrict__ link_b1,
                            const float* __restrict__ msg_w,
                            const float* __restrict__ msg_b,
                            const float* __restrict__ gru_w_hh,
                            const float* __restrict__ gru_b_hh) {
    int idx = blockIdx.x * blockDim.x + threadIdx.x;
    int stride = gridDim.x * blockDim.x;
    // Wab: 524 x 262
    for (int i = idx; i < DD2 * DD; i += stride) {
        int n = i / DD, k = i % DD;
        g_Wab[i] = (n < DD) ? link_w1[n * DD2 + k]
                            : link_w1[(n - DD) * DD2 + DD + k];
    }
    // Wmg: 914 x 262
    for (int i = idx; i < NMG * DD; i += stride) {
        int n = i / DD, k = i % DD;
        g_Wmg[i] = (n < MSGD) ? msg_w[n * DD + k] : gru_w_hh[(n - MSGD) * DD + k];
    }
    for (int i = idx; i < DD2; i += stride) g_bab[i] = (i < DD) ? link_b1[i] : 0.0f;
    for (int i = idx; i < NMG; i += stride) g_bmg[i] = (i < MSGD) ? msg_b[i] : gru_b_hh[i - MSGD];
}

// ---------------- GEMM: C = A * W^T + bias ----------------
// 128x128 tile, 256 threads, 8x8 microtile. M == 2048 exactly (no M guards).
// A: 2048 x K (lda), W: N x K (ldw), C: 2048 x N (ldc).
#define BM 128
#define BN 128
#define BK 16
__global__ __launch_bounds__(256) void gemm_kernel(
        const float* __restrict__ A, int lda,
        const float* __restrict__ W, int ldw,
        const float* __restrict__ bias,
        float* __restrict__ C, int ldc, int N, int K) {
    __shared__ float As[BK][BM];
    __shared__ float Ws[BK][BN];
    int tid = threadIdx.x;
    int tx = tid & 15, ty = tid >> 4;          // 16x16 thread grid
    int m0 = blockIdx.y * BM, n0 = blockIdx.x * BN;

    int half = tid >> 7;                        // 0/1
    int lrow = tid & 127;
    int kc = half * 8;

    const float* ap = A + (size_t)(m0 + lrow) * lda + kc;
    int wn = n0 + lrow;
    int wrow = (wn < N) ? wn : (N - 1);          // clamp; bogus cols never stored
    const float* wp = W + (size_t)wrow * ldw + kc;

    float acc[8][8] = {};

    for (int k0 = 0; k0 < K; k0 += BK) {
        float va[8], vw[8];
        if (k0 + BK <= K) {
            #pragma unroll
            for (int j = 0; j < 8; j += 2) {
                float2 t = *(const float2*)(ap + k0 + j);
                va[j] = t.x; va[j + 1] = t.y;
                float2 u = *(const float2*)(wp + k0 + j);
                vw[j] = u.x; vw[j + 1] = u.y;
            }
        } else {
            #pragma unroll
            for (int j = 0; j < 8; j++) {
                int k = k0 + kc + j;
                va[j] = (k < K) ? ap[k0 + j] : 0.0f;
                vw[j] = (k < K) ? wp[k0 + j] : 0.0f;
            }
        }
        __syncthreads();
        #pragma unroll
        for (int j = 0; j < 8; j++) {
            As[kc + j][lrow] = va[j];
            Ws[kc + j][lrow] = vw[j];
        }
        __syncthreads();
        #pragma unroll
        for (int kk = 0; kk < BK; kk++) {
            float a[8], w[8];
            *(float4*)&a[0] = *(const float4*)&As[kk][ty * 8];
            *(float4*)&a[4] = *(const float4*)&As[kk][ty * 8 + 4];
            *(float4*)&w[0] = *(const float4*)&Ws[kk][tx * 8];
            *(float4*)&w[4] = *(const float4*)&Ws[kk][tx * 8 + 4];
            #pragma unroll
            for (int i = 0; i < 8; i++)
                #pragma unroll
                for (int j = 0; j < 8; j++)
                    acc[i][j] = fmaf(a[i], w[j], acc[i][j]);
        }
    }

    #pragma unroll
    for (int i = 0; i < 8; i++) {
        int m = m0 + ty * 8 + i;
        #pragma unroll
        for (int j = 0; j < 8; j++) {
            int n = n0 + tx * 8 + j;
            if (n < N) C[(size_t)m * ldc + n] = acc[i][j] + bias[n];
        }
    }
}

// ---------------- attention: warp per (b,n,w) pair, float2 loads ----------------
__global__ void att_kernel(const float* __restrict__ b1,
                           const float* __restrict__ w2,
                           const float* __restrict__ b2v,
                           const int* __restrict__ num_rec,
                           float* __restrict__ att_out) {
    int gw = (blockIdx.x * blockDim.x + threadIdx.x) >> 5;
    int lane = threadIdx.x & 31;
    if (gw >= NB * MB * MB) return;
    int b = gw >> 10, n = (gw >> 5) & 31, w = gw & 31;
    int nr = num_rec[b];
    bool valid = (n < nr) && (w < nr);

    // valid: A-row (already has +b1) and raw B-row; invalid: relu(b1)·w2
    const float2* ra = valid ? (const float2*)(g_AB + (size_t)(b * MB + n) * DD2)
                             : (const float2*)b1;
    const float2* rb = valid ? (const float2*)(g_AB + (size_t)(b * MB + w) * DD2 + DD)
                             : (const float2*)g_zero;
    const float2* wv = (const float2*)w2;

    float s = 0.0f;
    #pragma unroll 1
    for (int i = lane; i < DD / 2; i += 32) {      // 131 float2
        float2 a = ra[i], bb = rb[i], ww = wv[i];
        s = fmaf(fmaxf(a.x + bb.x, 0.0f), ww.x, s);
        s = fmaf(fmaxf(a.y + bb.y, 0.0f), ww.y, s);
    }
    #pragma unroll
    for (int o = 16; o > 0; o >>= 1) s += __shfl_xor_sync(0xffffffffu, s, o);
    if (lane == 0) {
        float a = sigmoidf(s + b2v[0]);
        g_att[gw] = a;
        att_out[gw] = a;
    }
}

// ---------------- mv[b,n,k] = sum_{w < nr_b} att[b,n,w] * msg[b,w,k] ----------------
__global__ void mv_kernel(const int* __restrict__ num_rec) {
    int bn = blockIdx.x;              // 0..2047
    int b = bn >> 5;
    int k = threadIdx.x;              // 0..127
    int nr = num_rec[b];
    const float* arow = g_att + (size_t)bn * MB;
    const float* mb = g_mg + (size_t)b * MB * NMG;   // msg cols [0,128)
    float s = 0.0f;
    for (int w = 0; w < nr; w++) s = fmaf(arow[w], mb[(size_t)w * NMG + k], s);
    g_mv[(size_t)bn * MSGD + k] = s;
}

// ---------------- GRU combine (in-place h update, vmask) ----------------
__global__ void gru_kernel(const int* __restrict__ num_rec) {
    int idx = blockIdx.x * blockDim.x + threadIdx.x;
    if (idx >= NM * DD) return;
    int row = idx / DD, d = idx % DD;
    int b = row >> 5, m = row & 31;
    size_t bx = (size_t)row * G3;
    size_t bh = (size_t)row * NMG + MSGD;
    float xr = g_gx[bx + d];
    float xz = g_gx[bx + DD + d];
    float xn = g_gx[bx + 2 * DD + d];
    float hr = g_mg[bh + d];
    float hz = g_mg[bh + DD + d];
    float hn = g_mg[bh + 2 * DD + d];
    float r = sigmoidf(xr + hr);
    float z = sigmoidf(xz + hz);
    float c = tanhf(xn + r * hn);
    float hv = g_h[idx];
    float out = (1.0f - z) * c + z * hv;
    g_h[idx] = (m < num_rec[b]) ? out : 0.0f;
}

// ---------------- fused readout: t = relu(h@ro_w1^T+b1); pred = t@ro_w2^T+b2 ----------------
#define SH_LD 266
#define ST_LD 133
__global__ void readout_kernel(const float* __restrict__ ro_w1,
                               const float* __restrict__ ro_b1,
                               const float* __restrict__ ro_w2,
                               const float* __restrict__ ro_b2,
                               const int* __restrict__ num_rec,
                               float* __restrict__ out) {
    extern __shared__ float s[];
    float* sh = s;                    // 32 x 266
    float* st = s + MB * SH_LD;       // 32 x 133
    int b = blockIdx.x;
    int tid = threadIdx.x;            // 0..511
    int lane = tid & 31, wid = tid >> 5;   // 16 warps

    for (int i = tid; i < MB * DD; i += 512) {
        int r = i / DD, d = i % DD;
        sh[r * SH_LD + d] = g_h[(size_t)(b * MB + r) * DD + d];
    }
    __syncthreads();

    // each warp computes 8 output cols; lane = row
    int r = lane;
    #pragma unroll 1
    for (int j = 0; j < 8; j++) {
        int k = wid * 8 + j;
        const float2* wrow = (const float2*)(ro_w1 + (size_t)k * DD);
        const float2* hrow = (const float2*)(sh + r * SH_LD);
        float acc = 0.0f;
        #pragma unroll 4
        for (int i = 0; i < DD / 2; i++) {
            float2 ww = __ldg(wrow + i);
            float2 hh = hrow[i];
            acc = fmaf(hh.x, ww.x, acc);
            acc = fmaf(hh.y, ww.y, acc);
        }
        st[r * ST_LD + k] = fmaxf(acc + ro_b1[k], 0.0f);
    }
    __syncthreads();

    if (tid < MB * NCLSD) {
        int rr = tid / NCLSD, c = tid % NCLSD;
        int nr = num_rec[b];
        float acc = ro_b2[c];
        #pragma unroll 4
        for (int k = 0; k < MSGD; k++)
            acc = fmaf(st[rr * ST_LD + k], __ldg(ro_w2 + (size_t)c * MSGD + k), acc);
        out[(size_t)(b * MB + rr) * NCLSD + c] = (rr < nr) ? acc : 0.0f;
    }
}

// ---------------- host launcher ----------------
static void launch_gemm(const float* A, int lda, const float* W, int ldw,
                        const float* bias, float* C, int ldc, int N, int K) {
    dim3 grid((N + BN - 1) / BN, NM / BM);
    gemm_kernel<<<grid, 256>>>(A, lda, W, ldw, bias, C, ldc, N, K);
}

extern "C" void kernel_launch(void* const* d_in, const int* in_sizes, int n_in,
                              void* d_out, int out_size) {
    const float* feat    = (const float*)d_in[0];
    const float* pos     = (const float*)d_in[1];
    const int*   num_rec = (const int*)  d_in[2];
    const float* link_w1 = (const float*)d_in[3];
    const float* link_b1 = (const float*)d_in[4];
    const float* link_w2 = (const float*)d_in[5];
    const float* link_b2 = (const float*)d_in[6];
    const float* msg_w   = (const float*)d_in[7];
    const float* msg_b   = (const float*)d_in[8];
    const float* gru_w_ih= (const float*)d_in[9];
    const float* gru_w_hh= (const float*)d_in[10];
    const float* gru_b_ih= (const float*)d_in[11];
    const float* gru_b_hh= (const float*)d_in[12];
    const float* ro_w1   = (const float*)d_in[13];
    const float* ro_b1   = (const float*)d_in[14];
    const float* ro_w2   = (const float*)d_in[15];
    const float* ro_b2   = (const float*)d_in[16];
    float* out = (float*)d_out;           // [pred (64*32*7) | attmat (64*32*32)]

    float *p_nf, *p_h, *p_AB, *p_Wab, *p_bab, *p_Wmg, *p_bmg, *p_mg, *p_mv, *p_gx;
    cudaGetSymbolAddress((void**)&p_nf,  g_nf);
    cudaGetSymbolAddress((void**)&p_h,   g_h);
    cudaGetSymbolAddress((void**)&p_AB,  g_AB);
    cudaGetSymbolAddress((void**)&p_Wab, g_Wab);
    cudaGetSymbolAddress((void**)&p_bab, g_bab);
    cudaGetSymbolAddress((void**)&p_Wmg, g_Wmg);
    cudaGetSymbolAddress((void**)&p_bmg, g_bmg);
    cudaGetSymbolAddress((void**)&p_mg,  g_mg);
    cudaGetSymbolAddress((void**)&p_mv,  g_mv);
    cudaGetSymbolAddress((void**)&p_gx,  g_gx);

    static const size_t RO_SMEM = (size_t)(MB * SH_LD + MB * ST_LD) * sizeof(float);
    cudaFuncSetAttribute(readout_kernel, cudaFuncAttributeMaxDynamicSharedMemorySize,
                         (int)RO_SMEM);

    // 1) nf = [feat, pos]; h = nf; pack fused weights
    build_nf_kernel<<<(NM * DD + 255) / 256, 256>>>(feat, pos);
    pack_kernel<<<296, 256>>>(link_w1, link_b1, msg_w, msg_b, gru_w_hh, gru_b_hh);

    // 2) edge MLP low-rank: AB = nf @ Wab^T + [b1|0]   (2048 x 524)
    launch_gemm(p_nf, DD, p_Wab, DD, p_bab, p_AB, DD2, DD2, DD);

    // 3) attention (writes scratch + output attmat region)
    {
        int threads = NB * MB * MB * 32;      // warp per pair
        att_kernel<<<(threads + 255) / 256, 256>>>(link_b1, link_w2, link_b2,
                                                   num_rec, out + NM * NCLSD);
    }

    // 4) two message-passing GRU rounds
    for (int round = 0; round < 2; round++) {
        launch_gemm(p_h,  DD,   p_Wmg,    DD,   p_bmg,    p_mg, NMG, NMG, DD);   // [msg|gh]
        mv_kernel<<<NM, MSGD>>>(num_rec);
        launch_gemm(p_mv, MSGD, gru_w_ih, MSGD, gru_b_ih, p_gx, G3,  G3,  MSGD); // gx
        gru_kernel<<<(NM * DD + 255) / 256, 256>>>(num_rec);
    }

    // 5) fused readout
    readout_kernel<<<NB, 512, RO_SMEM>>>(ro_w1, ro_b1, ro_w2, ro_b2, num_rec, out);

    (void)in_sizes; (void)n_in; (void)out_size;
}

// round 5
// speedup vs baseline: 2.4390x; 1.6546x over previous
#include <cuda_runtime.h>
#include <math.h>
#include <stdint.h>

#define NB 64
#define MB 32
#define NM (NB*MB)      // 2048 node rows
#define FEATD 256
#define POSD 6
#define DD 262
#define DD2 524
#define MSGD 128
#define NCLSD 7
#define G3 (3*DD)       // 786
#define NMG (MSGD + G3) // 914 fused msg|gh width

// ---------------- scratch (static device memory; zero-initialized) ----------------
__device__ float g_nf  [NM*DD];
__device__ float g_h   [NM*DD];
__device__ float g_AB  [NM*DD2];        // [A+b1 | B] per row, stride 524
__device__ float g_Wab [DD2*DD];        // packed [W1a; W1b]
__device__ float g_bab [DD2];           // [b1 | 0]
__device__ float g_Wmg [NMG*DD];        // packed [msg_w; gru_w_hh]
__device__ float g_bmg [NMG];           // [msg_b | gru_b_hh]
__device__ float g_mg  [NM*NMG];        // [msg | gh], stride 914
__device__ float g_att [NB*MB*MB];
__device__ float g_mv  [NM*MSGD];
__device__ float g_gx  [NM*G3];
__device__ float g_zero[DD];            // stays zero forever

__device__ __forceinline__ float sigmoidf(float x) {
    return 1.0f / (1.0f + expf(-x));
}
__device__ __forceinline__ uint32_t f2tf(float v) {
    uint32_t r; asm("cvt.rna.tf32.f32 %0, %1;" : "=r"(r) : "f"(v)); return r;
}
__device__ __forceinline__ void mma_tf32(float* c, const uint32_t* a, const uint32_t* b) {
    asm volatile(
        "mma.sync.aligned.m16n8k8.row.col.f32.tf32.tf32.f32 "
        "{%0,%1,%2,%3}, {%4,%5,%6,%7}, {%8,%9}, {%0,%1,%2,%3};\n"
        : "+f"(c[0]), "+f"(c[1]), "+f"(c[2]), "+f"(c[3])
        : "r"(a[0]), "r"(a[1]), "r"(a[2]), "r"(a[3]), "r"(b[0]), "r"(b[1]));
}

// ---------------- build nf = [feat, pos], h = nf ----------------
__global__ void build_nf_kernel(const float* __restrict__ feat,
                                const float* __restrict__ pos) {
    int idx = blockIdx.x * blockDim.x + threadIdx.x;
    if (idx >= NM * DD) return;
    int row = idx / DD, c = idx % DD;
    float v = (c < FEATD) ? feat[row * FEATD + c] : pos[row * POSD + (c - FEATD)];
    g_nf[idx] = v;
    g_h[idx]  = v;
}

// ---------------- pack fused weight/bias buffers ----------------
__global__ void pack_kernel(const float* __restrict__ link_w1,
                            const float* __restrict__ link_b1,
                            const float* __restrict__ msg_w,
                            const float* __restrict__ msg_b,
                            const float* __restrict__ gru_w_hh,
                            const float* __restrict__ gru_b_hh) {
    int idx = blockIdx.x * blockDim.x + threadIdx.x;
    int stride = gridDim.x * blockDim.x;
    for (int i = idx; i < DD2 * DD; i += stride) {
        int n = i / DD, k = i % DD;
        g_Wab[i] = (n < DD) ? link_w1[n * DD2 + k]
                            : link_w1[(n - DD) * DD2 + DD + k];
    }
    for (int i = idx; i < NMG * DD; i += stride) {
        int n = i / DD, k = i % DD;
        g_Wmg[i] = (n < MSGD) ? msg_w[n * DD + k] : gru_w_hh[(n - MSGD) * DD + k];
    }
    for (int i = idx; i < DD2; i += stride) g_bab[i] = (i < DD) ? link_b1[i] : 0.0f;
    for (int i = idx; i < NMG; i += stride) g_bmg[i] = (i < MSGD) ? msg_b[i] : gru_b_hh[i - MSGD];
}

// ---------------- TF32 tensor-core GEMM: C = A * W^T + bias ----------------
// A: 2048 x K (lda, fp32, lda EVEN), W: N x K (ldw EVEN), C: 2048 x N (ldc EVEN).
// Block tile 64x128 (8 warps, warp tile 32x32 via m16n8k8).
#define BM 64
#define BN 128
#define BK 32
#define ASLD 36
#define WSLD 36
__global__ __launch_bounds__(256) void gemm_tc_kernel(
        const float* __restrict__ A, int lda,
        const float* __restrict__ W, int ldw,
        const float* __restrict__ bias,
        float* __restrict__ C, int ldc, int N, int K) {
    __shared__ uint32_t As[BM * ASLD];
    __shared__ uint32_t Ws[BN * WSLD];

    int tid = threadIdx.x;
    int warp = tid >> 5, lane = tid & 31;
    int gid = lane >> 2, tig = lane & 3;
    int wm = (warp >> 2) * 32;       // 0 or 32
    int wn = (warp & 3) * 32;        // 0,32,64,96
    int m0 = blockIdx.y * BM, n0 = blockIdx.x * BN;

    // G->S load mapping
    int arow = tid >> 2, akc = (tid & 3) * 8;      // A: 64 rows x 32 k, 8 each
    int wrow = tid >> 1, wkc = (tid & 1) * 16;     // W: 128 rows x 32 k, 16 each
    int wng = n0 + wrow;
    int wclamp = (wng < N) ? wng : (N - 1);
    const float* ap = A + (size_t)(m0 + arow) * lda + akc;
    const float* wp = W + (size_t)wclamp * ldw + wkc;

    float acc[2][4][4];
    #pragma unroll
    for (int i = 0; i < 2; i++)
        #pragma unroll
        for (int j = 0; j < 4; j++)
            #pragma unroll
            for (int q = 0; q < 4; q++) acc[i][j][q] = 0.0f;

    int nk = (K + BK - 1) / BK;
    float va[8], vw[16];

    // prefetch slab 0 (float2 only: strides are even but not /4)
    {
        if (BK <= K) {
            #pragma unroll
            for (int j = 0; j < 8; j += 2) {
                float2 t = *(const float2*)(ap + j);
                va[j] = t.x; va[j + 1] = t.y;
            }
            #pragma unroll
            for (int j = 0; j < 16; j += 2) {
                float2 u = *(const float2*)(wp + j);
                vw[j] = u.x; vw[j + 1] = u.y;
            }
        } else {
            #pragma unroll
            for (int j = 0; j < 8; j++)  va[j] = (akc + j < K) ? ap[j] : 0.0f;
            #pragma unroll
            for (int j = 0; j < 16; j++) vw[j] = (wkc + j < K) ? wp[j] : 0.0f;
        }
    }

    for (int it = 0; it < nk; it++) {
        __syncthreads();
        // store staged slab (tf32-converted, vectorized smem stores — 16B aligned)
        {
            uint32_t* ad = As + arow * ASLD + akc;
            uint4 p0 = make_uint4(f2tf(va[0]), f2tf(va[1]), f2tf(va[2]), f2tf(va[3]));
            uint4 p1 = make_uint4(f2tf(va[4]), f2tf(va[5]), f2tf(va[6]), f2tf(va[7]));
            *(uint4*)(ad)     = p0;
            *(uint4*)(ad + 4) = p1;
            uint32_t* wd = Ws + wrow * WSLD + wkc;
            #pragma unroll
            for (int j = 0; j < 16; j += 4) {
                uint4 q = make_uint4(f2tf(vw[j]), f2tf(vw[j+1]), f2tf(vw[j+2]), f2tf(vw[j+3]));
                *(uint4*)(wd + j) = q;
            }
        }
        __syncthreads();

        // prefetch next slab
        if (it + 1 < nk) {
            int k0 = (it + 1) * BK;
            if (k0 + BK <= K) {
                #pragma unroll
                for (int j = 0; j < 8; j += 2) {
                    float2 t = *(const float2*)(ap + k0 + j);
                    va[j] = t.x; va[j + 1] = t.y;
                }
                #pragma unroll
                for (int j = 0; j < 16; j += 2) {
                    float2 u = *(const float2*)(wp + k0 + j);
                    vw[j] = u.x; vw[j + 1] = u.y;
                }
            } else {
                #pragma unroll
                for (int j = 0; j < 8; j++)  va[j] = (k0 + akc + j < K) ? ap[k0 + j] : 0.0f;
                #pragma unroll
                for (int j = 0; j < 16; j++) vw[j] = (k0 + wkc + j < K) ? wp[k0 + j] : 0.0f;
            }
        }

        // compute: 4 k-steps of 8
        #pragma unroll
        for (int ks = 0; ks < 4; ks++) {
            int kb = ks * 8;
            uint32_t af[2][4];
            #pragma unroll
            for (int mf = 0; mf < 2; mf++) {
                const uint32_t* b0 = As + (wm + mf * 16 + gid) * ASLD + kb + tig;
                af[mf][0] = b0[0];
                af[mf][1] = b0[8 * ASLD];
                af[mf][2] = b0[4];
                af[mf][3] = b0[8 * ASLD + 4];
            }
            uint32_t bf[4][2];
            #pragma unroll
            for (int nf = 0; nf < 4; nf++) {
                const uint32_t* b0 = Ws + (wn + nf * 8 + gid) * WSLD + kb + tig;
                bf[nf][0] = b0[0];
                bf[nf][1] = b0[4];
            }
            #pragma unroll
            for (int mf = 0; mf < 2; mf++)
                #pragma unroll
                for (int nf = 0; nf < 4; nf++)
                    mma_tf32(acc[mf][nf], af[mf], bf[nf]);
        }
    }

    // epilogue: c0,c1 -> row (gid) cols 2t,2t+1 ; c2,c3 -> row (gid+8)
    #pragma unroll
    for (int nf = 0; nf < 4; nf++) {
        int col = n0 + wn + nf * 8 + tig * 2;
        if (col >= N) continue;
        float2 bv = *(const float2*)(bias + col);
        #pragma unroll
        for (int mf = 0; mf < 2; mf++) {
            int r0 = m0 + wm + mf * 16 + gid;
            float2 v0 = make_float2(acc[mf][nf][0] + bv.x, acc[mf][nf][1] + bv.y);
            float2 v1 = make_float2(acc[mf][nf][2] + bv.x, acc[mf][nf][3] + bv.y);
            *(float2*)(C + (size_t)r0 * ldc + col) = v0;
            *(float2*)(C + (size_t)(r0 + 8) * ldc + col) = v1;
        }
    }
}

// ---------------- attention: warp per (b,n,w) pair, float2 loads ----------------
__global__ void att_kernel(const float* __restrict__ b1,
                           const float* __restrict__ w2,
                           const float* __restrict__ b2v,
                           const int* __restrict__ num_rec,
                           float* __restrict__ att_out) {
    int gw = (blockIdx.x * blockDim.x + threadIdx.x) >> 5;
    int lane = threadIdx.x & 31;
    if (gw >= NB * MB * MB) return;
    int b = gw >> 10, n = (gw >> 5) & 31, w = gw & 31;
    int nr = num_rec[b];
    bool valid = (n < nr) && (w < nr);

    const float2* ra = valid ? (const float2*)(g_AB + (size_t)(b * MB + n) * DD2)
                             : (const float2*)b1;
    const float2* rb = valid ? (const float2*)(g_AB + (size_t)(b * MB + w) * DD2 + DD)
                             : (const float2*)g_zero;
    const float2* wv = (const float2*)w2;

    float s = 0.0f;
    #pragma unroll 1
    for (int i = lane; i < DD / 2; i += 32) {
        float2 a = ra[i], bb = rb[i], ww = wv[i];
        s = fmaf(fmaxf(a.x + bb.x, 0.0f), ww.x, s);
        s = fmaf(fmaxf(a.y + bb.y, 0.0f), ww.y, s);
    }
    #pragma unroll
    for (int o = 16; o > 0; o >>= 1) s += __shfl_xor_sync(0xffffffffu, s, o);
    if (lane == 0) {
        float a = sigmoidf(s + b2v[0]);
        g_att[gw] = a;
        att_out[gw] = a;
    }
}

// ---------------- mv[b,n,k] = sum_{w < nr_b} att[b,n,w] * msg[b,w,k] ----------------
__global__ void mv_kernel(const int* __restrict__ num_rec) {
    int bn = blockIdx.x;
    int b = bn >> 5;
    int k = threadIdx.x;              // 0..127
    int nr = num_rec[b];
    const float* arow = g_att + (size_t)bn * MB;
    const float* mb = g_mg + (size_t)b * MB * NMG;
    float s = 0.0f;
    for (int w = 0; w < nr; w++) s = fmaf(arow[w], mb[(size_t)w * NMG + k], s);
    g_mv[(size_t)bn * MSGD + k] = s;
}

// ---------------- GRU combine (in-place h update, vmask) ----------------
__global__ void gru_kernel(const int* __restrict__ num_rec) {
    int idx = blockIdx.x * blockDim.x + threadIdx.x;
    if (idx >= NM * DD) return;
    int row = idx / DD, d = idx % DD;
    int b = row >> 5, m = row & 31;
    size_t bx = (size_t)row * G3;
    size_t bh = (size_t)row * NMG + MSGD;
    float xr = g_gx[bx + d];
    float xz = g_gx[bx + DD + d];
    float xn = g_gx[bx + 2 * DD + d];
    float hr = g_mg[bh + d];
    float hz = g_mg[bh + DD + d];
    float hn = g_mg[bh + 2 * DD + d];
    float r = sigmoidf(xr + hr);
    float z = sigmoidf(xz + hz);
    float c = tanhf(xn + r * hn);
    float hv = g_h[idx];
    float out = (1.0f - z) * c + z * hv;
    g_h[idx] = (m < num_rec[b]) ? out : 0.0f;
}

// ---------------- fused readout ----------------
#define SH_LD 266
#define ST_LD 133
__global__ void readout_kernel(const float* __restrict__ ro_w1,
                               const float* __restrict__ ro_b1,
                               const float* __restrict__ ro_w2,
                               const float* __restrict__ ro_b2,
                               const int* __restrict__ num_rec,
                               float* __restrict__ out) {
    extern __shared__ float s[];
    float* sh = s;                    // 32 x 266
    float* st = s + MB * SH_LD;       // 32 x 133
    int b = blockIdx.x;
    int tid = threadIdx.x;            // 0..511
    int lane = tid & 31, wid = tid >> 5;

    for (int i = tid; i < MB * DD; i += 512) {
        int r = i / DD, d = i % DD;
        sh[r * SH_LD + d] = g_h[(size_t)(b * MB + r) * DD + d];
    }
    __syncthreads();

    int r = lane;
    #pragma unroll 1
    for (int j = 0; j < 8; j++) {
        int k = wid * 8 + j;
        const float2* wrow = (const float2*)(ro_w1 + (size_t)k * DD);
        const float2* hrow = (const float2*)(sh + r * SH_LD);
        float acc = 0.0f;
        #pragma unroll 4
        for (int i = 0; i < DD / 2; i++) {
            float2 ww = __ldg(wrow + i);
            float2 hh = hrow[i];
            acc = fmaf(hh.x, ww.x, acc);
            acc = fmaf(hh.y, ww.y, acc);
        }
        st[r * ST_LD + k] = fmaxf(acc + ro_b1[k], 0.0f);
    }
    __syncthreads();

    if (tid < MB * NCLSD) {
        int rr = tid / NCLSD, c = tid % NCLSD;
        int nr = num_rec[b];
        float acc = ro_b2[c];
        #pragma unroll 4
        for (int k = 0; k < MSGD; k++)
            acc = fmaf(st[rr * ST_LD + k], __ldg(ro_w2 + (size_t)c * MSGD + k), acc);
        out[(size_t)(b * MB + rr) * NCLSD + c] = (rr < nr) ? acc : 0.0f;
    }
}

// ---------------- host launcher ----------------
static void launch_gemm(const float* A, int lda, const float* W, int ldw,
                        const float* bias, float* C, int ldc, int N, int K) {
    dim3 grid((N + BN - 1) / BN, NM / BM);
    gemm_tc_kernel<<<grid, 256>>>(A, lda, W, ldw, bias, C, ldc, N, K);
}

extern "C" void kernel_launch(void* const* d_in, const int* in_sizes, int n_in,
                              void* d_out, int out_size) {
    const float* feat    = (const float*)d_in[0];
    const float* pos     = (const float*)d_in[1];
    const int*   num_rec = (const int*)  d_in[2];
    const float* link_w1 = (const float*)d_in[3];
    const float* link_b1 = (const float*)d_in[4];
    const float* link_w2 = (const float*)d_in[5];
    const float* link_b2 = (const float*)d_in[6];
    const float* msg_w   = (const float*)d_in[7];
    const float* msg_b   = (const float*)d_in[8];
    const float* gru_w_ih= (const float*)d_in[9];
    const float* gru_w_hh= (const float*)d_in[10];
    const float* gru_b_ih= (const float*)d_in[11];
    const float* gru_b_hh= (const float*)d_in[12];
    const float* ro_w1   = (const float*)d_in[13];
    const float* ro_b1   = (const float*)d_in[14];
    const float* ro_w2   = (const float*)d_in[15];
    const float* ro_b2   = (const float*)d_in[16];
    float* out = (float*)d_out;           // [pred (64*32*7) | attmat (64*32*32)]

    float *p_nf, *p_h, *p_AB, *p_Wab, *p_bab, *p_Wmg, *p_bmg, *p_mg, *p_mv, *p_gx;
    cudaGetSymbolAddress((void**)&p_nf,  g_nf);
    cudaGetSymbolAddress((void**)&p_h,   g_h);
    cudaGetSymbolAddress((void**)&p_AB,  g_AB);
    cudaGetSymbolAddress((void**)&p_Wab, g_Wab);
    cudaGetSymbolAddress((void**)&p_bab, g_bab);
    cudaGetSymbolAddress((void**)&p_Wmg, g_Wmg);
    cudaGetSymbolAddress((void**)&p_bmg, g_bmg);
    cudaGetSymbolAddress((void**)&p_mg,  g_mg);
    cudaGetSymbolAddress((void**)&p_mv,  g_mv);
    cudaGetSymbolAddress((void**)&p_gx,  g_gx);

    static const size_t RO_SMEM = (size_t)(MB * SH_LD + MB * ST_LD) * sizeof(float);
    cudaFuncSetAttribute(readout_kernel, cudaFuncAttributeMaxDynamicSharedMemorySize,
                         (int)RO_SMEM);

    // 1) nf = [feat, pos]; h = nf; pack fused weights
    build_nf_kernel<<<(NM * DD + 255) / 256, 256>>>(feat, pos);
    pack_kernel<<<296, 256>>>(link_w1, link_b1, msg_w, msg_b, gru_w_hh, gru_b_hh);

    // 2) edge MLP low-rank: AB = nf @ Wab^T + [b1|0]   (2048 x 524)
    launch_gemm(p_nf, DD, p_Wab, DD, p_bab, p_AB, DD2, DD2, DD);

    // 3) attention
    {
        int threads = NB * MB * MB * 32;
        att_kernel<<<(threads + 255) / 256, 256>>>(link_b1, link_w2, link_b2,
                                                   num_rec, out + NM * NCLSD);
    }

    // 4) two message-passing GRU rounds
    for (int round = 0; round < 2; round++) {
        launch_gemm(p_h,  DD,   p_Wmg,    DD,   p_bmg,    p_mg, NMG, NMG, DD);
        mv_kernel<<<NM, MSGD>>>(num_rec);
        launch_gemm(p_mv, MSGD, gru_w_ih, MSGD, gru_b_ih, p_gx, G3,  G3,  MSGD);
        gru_kernel<<<(NM * DD + 255) / 256, 256>>>(num_rec);
    }

    // 5) fused readout
    readout_kernel<<<NB, 512, RO_SMEM>>>(ro_w1, ro_b1, ro_w2, ro_b2, num_rec, out);

    (void)in_sizes; (void)n_in; (void)out_size;
}